// round 10
// baseline (speedup 1.0000x reference)
#include <cuda_runtime.h>
#include <cuda_bf16.h>
#include <math.h>
#include <stdint.h>

// PCL loss, single kernel. The coalesced 24 MB (target/cluster/weight) moves
// via cp.async.bulk (TMA-1D) into smem — bypassing the per-SM L1tex
// outstanding-miss cap that limited every LDG variant to ~2.7 TB/s. Only the
// small scattered gathers (t==0 input column + L1-resident pc table) use LDG.
//
//   valid = target != -1
//   p     = (target==0) ? input[i*21] : pc_input[cluster[i]]
//   loss  = sum(valid * (-w * log(max(p,1e-12)))) / max(sum(valid),1)

#define C_CLASSES 21
#define EPS 1e-12f
#define THREADS 256
#define STAGE_ELEMS 1024
#define STAGES 4
#define CTA_ELEMS (STAGE_ELEMS * STAGES)        // 4096
#define STAGE_BYTES (STAGE_ELEMS * 4)           // 4096 B per array per stage
#define STAGE_TX (3 * STAGE_BYTES)              // 12288 B per stage

// dynamic smem layout (bytes):
//   [0,      16384)  t_s  : 4 stages x 1024 int
//   [16384,  32768)  c_s  : 4 stages x 1024 int
//   [32768,  49152)  w_s  : 4 stages x 1024 float
//   [49152,  49184)  mbar : 4 x u64
#define SMEM_T    0
#define SMEM_C    16384
#define SMEM_W    32768
#define SMEM_MBAR 49152
#define SMEM_DYN  49408

__device__ float        g_sum = 0.0f;
__device__ unsigned int g_cnt = 0u;
__device__ unsigned int g_done = 0u;   // wraps to 0 via atom.inc bound

__device__ __forceinline__ uint32_t smem_u32(const void* p) {
    uint32_t a;
    asm("{ .reg .u64 t; cvta.to.shared.u64 t, %1; cvt.u32.u64 %0, t; }"
        : "=r"(a) : "l"(p));
    return a;
}

__device__ __forceinline__ void mbar_init(uint32_t mbar, uint32_t count) {
    asm volatile("mbarrier.init.shared.b64 [%0], %1;" :: "r"(mbar), "r"(count) : "memory");
}
__device__ __forceinline__ void mbar_expect_tx(uint32_t mbar, uint32_t bytes) {
    asm volatile("mbarrier.arrive.expect_tx.shared.b64 _, [%0], %1;"
                 :: "r"(mbar), "r"(bytes) : "memory");
}
__device__ __forceinline__ void bulk_g2s(uint32_t dst, const void* src,
                                         uint32_t bytes, uint32_t mbar) {
    asm volatile("cp.async.bulk.shared::cta.global.mbarrier::complete_tx::bytes "
                 "[%0], [%1], %2, [%3];"
                 :: "r"(dst), "l"(src), "r"(bytes), "r"(mbar) : "memory");
}
__device__ __forceinline__ void mbar_wait(uint32_t mbar, uint32_t parity) {
    asm volatile(
        "{\n\t"
        ".reg .pred P;\n\t"
        "WAIT_%=:\n\t"
        "mbarrier.try_wait.parity.acquire.cta.shared::cta.b64 P, [%0], %1, 0x989680;\n\t"
        "@P bra.uni DONE_%=;\n\t"
        "bra.uni WAIT_%=;\n\t"
        "DONE_%=:\n\t"
        "}" :: "r"(mbar), "r"(parity) : "memory");
}

__global__ void __launch_bounds__(THREADS)
pcl_fused(const float* __restrict__ input,
          const float* __restrict__ weight,
          const float* __restrict__ pc,
          const int* __restrict__ target,
          const int* __restrict__ cluster,
          int n, float* __restrict__ out) {
    extern __shared__ char smem[];
    int*   t_s = (int*)(smem + SMEM_T);
    int*   c_s = (int*)(smem + SMEM_C);
    float* w_s = (float*)(smem + SMEM_W);
    const uint32_t mbar0 = smem_u32(smem + SMEM_MBAR);

    float lsum = 0.0f;
    unsigned int lcnt = 0u;

    const int base = blockIdx.x * CTA_ELEMS;
    const bool full = (base + CTA_ELEMS <= n);

    if (full) {
        if (threadIdx.x == 0) {
            #pragma unroll
            for (int s = 0; s < STAGES; s++) mbar_init(mbar0 + 8 * s, 1);
            asm volatile("fence.proxy.async.shared::cta;" ::: "memory");
        }
        __syncthreads();
        if (threadIdx.x == 0) {
            // issue ALL stages up front: 12 bulk copies in flight (TMA path,
            // no L1tex miss-queue occupancy)
            #pragma unroll
            for (int s = 0; s < STAGES; s++) {
                uint32_t mb = mbar0 + 8 * s;
                mbar_expect_tx(mb, STAGE_TX);
                int off = base + s * STAGE_ELEMS;
                bulk_g2s(smem_u32(t_s + s * STAGE_ELEMS), target  + off, STAGE_BYTES, mb);
                bulk_g2s(smem_u32(c_s + s * STAGE_ELEMS), cluster + off, STAGE_BYTES, mb);
                bulk_g2s(smem_u32(w_s + s * STAGE_ELEMS), weight  + off, STAGE_BYTES, mb);
            }
        }

        #pragma unroll
        for (int s = 0; s < STAGES; s++) {
            mbar_wait(mbar0 + 8 * s, 0);
            const int i = base + s * STAGE_ELEMS + threadIdx.x * 4;
            int4   t4 = ((const int4*)  (t_s + s * STAGE_ELEMS))[threadIdx.x];
            int4   c4 = ((const int4*)  (c_s + s * STAGE_ELEMS))[threadIdx.x];
            float4 w4 = ((const float4*)(w_s + s * STAGE_ELEMS))[threadIdx.x];

            int   t[4] = {t4.x, t4.y, t4.z, t4.w};
            int   c[4] = {c4.x, c4.y, c4.z, c4.w};
            float w[4] = {w4.x, w4.y, w4.z, w4.w};

            // branchless gather: only t==0 lanes touch the strided input
            // column; others hit the 16KB L1-resident pc table
            const float* addr[4];
            #pragma unroll
            for (int k = 0; k < 4; k++) {
                const float* a_bg = input + (long long)(i + k) * C_CLASSES;
                const float* a_fg = pc + c[k];
                addr[k] = (t[k] == 0) ? a_bg : a_fg;
            }
            float p[4];
            #pragma unroll
            for (int k = 0; k < 4; k++) p[k] = __ldg(addr[k]);

            #pragma unroll
            for (int k = 0; k < 4; k++) {
                bool valid = (t[k] != -1);
                float l = __logf(fmaxf(p[k], EPS));
                lsum += valid ? w[k] * l : 0.0f;
                lcnt += valid ? 1u : 0u;
            }
        }
    } else {
        // ragged tail CTA: plain LDG scalar path
        for (int k = base + threadIdx.x; k < n; k += THREADS) {
            int tk = target[k];
            if (tk != -1) {
                float pk = (tk == 0) ? __ldg(input + (long long)k * C_CLASSES)
                                     : __ldg(pc + cluster[k]);
                lsum += weight[k] * __logf(fmaxf(pk, EPS));
                lcnt++;
            }
        }
    }

    // warp reduction
    #pragma unroll
    for (int off = 16; off > 0; off >>= 1) {
        lsum += __shfl_xor_sync(0xFFFFFFFFu, lsum, off);
        lcnt += __shfl_xor_sync(0xFFFFFFFFu, lcnt, off);
    }

    // block reduction (8 warps)
    __shared__ float        s_sum[8];
    __shared__ unsigned int s_cnt[8];
    __shared__ int          s_is_last;
    int wid = threadIdx.x >> 5;
    int lid = threadIdx.x & 31;
    if (lid == 0) { s_sum[wid] = lsum; s_cnt[wid] = lcnt; }
    __syncthreads();
    if (threadIdx.x == 0) {
        float        bs = 0.0f;
        unsigned int bc = 0u;
        #pragma unroll
        for (int w8 = 0; w8 < 8; w8++) { bs += s_sum[w8]; bc += s_cnt[w8]; }
        // merge partials at the L2 coherence point (atomics bypass L1)
        atomicAdd(&g_sum, bs);
        atomicAdd(&g_cnt, bc);
        // release-only inc publishes the adds; wraps to 0 (replay-safe)
        unsigned int prev;
        asm volatile("atom.release.gpu.global.inc.u32 %0, [%1], %2;"
                     : "=r"(prev)
                     : "l"(&g_done), "r"(gridDim.x - 1)
                     : "memory");
        s_is_last = (prev == gridDim.x - 1) ? 1 : 0;
    }
    __syncthreads();

    if (s_is_last && threadIdx.x == 0) {
        // coherent reads at L2 — no acquire/L1-invalidate needed
        float        ts = atomicAdd(&g_sum, 0.0f);
        unsigned int tc = atomicAdd(&g_cnt, 0u);
        float nv = fmaxf((float)tc, 1.0f);
        *out = -ts / nv;
        g_sum = 0.0f;   // reset for next replay; kernel boundary orders this
        g_cnt = 0u;
    }
}

extern "C" void kernel_launch(void* const* d_in, const int* in_sizes, int n_in,
                              void* d_out, int out_size) {
    const float* input   = (const float*)d_in[0];   // [N, 21]
    const float* weight  = (const float*)d_in[1];   // [N]
    const float* pc      = (const float*)d_in[2];   // [4096]
    const int*   target  = (const int*)d_in[3];     // [N] int32
    const int*   cluster = (const int*)d_in[4];     // [N] int32
    float* out = (float*)d_out;

    int n = in_sizes[1];   // weight element count == N

    cudaFuncSetAttribute(pcl_fused,
                         cudaFuncAttributeMaxDynamicSharedMemorySize, SMEM_DYN);

    int blocks = (n + CTA_ELEMS - 1) / CTA_ELEMS;  // 512 for N=2M
    if (blocks < 1) blocks = 1;
    pcl_fused<<<blocks, THREADS, SMEM_DYN>>>(input, weight, pc, target,
                                             cluster, n, out);
}

// round 11
// speedup vs baseline: 1.4048x; 1.4048x over previous
#include <cuda_runtime.h>
#include <cuda_bf16.h>
#include <math.h>

// PCL loss, single kernel:
//   valid = target != -1
//   p     = (target==0) ? input[i*21] : pc_input[cluster[i]]
//   loss  = sum(valid * (-w * log(max(p,1e-12)))) / max(sum(valid),1)
//
// Design (R11):
//  * pc gathers via SHARED MEMORY (random LDS = bank-conflict degree ~4-5 cyc)
//    instead of LDG (divergent 30-sector warp-LDG = ~62 cyc of L1tex replay
//    occupancy each — the invariant 14us bottleneck of all LDG variants).
//  * background gather branchless: inactive lanes read input[0] (broadcast
//    sector) so the residual LDG path is ~1.5 real lines per warp-instr.
//  * 1024 CTAs, EPT=8 -> high occupancy AND tolerable table-staging cost.
//  * tail: atomicAdd partials at L2 + release-only inc (no acquire, no
//    CCTL.IVALL L1 flush), self-resetting counter, replay-deterministic.
//  * accumulate w*log2(p), multiply by ln2 once at the very end.

#define C_CLASSES 21
#define EPS 1e-12f
#define NUM_CLUSTERS 4096
#define THREADS 256
#define EPT 8
#define LN2F 0.6931471805599453f

__device__ float        g_sum = 0.0f;
__device__ unsigned int g_cnt = 0u;
__device__ unsigned int g_done = 0u;   // wraps to 0 via atom.inc bound

__global__ void __launch_bounds__(THREADS)
pcl_fused(const float* __restrict__ input,
          const float* __restrict__ weight,
          const float* __restrict__ pc,
          const int* __restrict__ target,
          const int* __restrict__ cluster,
          int n, float* __restrict__ out) {
    __shared__ float pc_s[NUM_CLUSTERS];

    // stage the 16KB pc table (L2-resident after first CTA): 4 float4/thread
    {
        const float4* src = reinterpret_cast<const float4*>(pc);
        #pragma unroll
        for (int k = 0; k < NUM_CLUSTERS / 4 / THREADS; k++) {
            int idx = k * THREADS + threadIdx.x;
            float4 v = __ldg(src + idx);
            *reinterpret_cast<float4*>(pc_s + idx * 4) = v;
        }
    }
    __syncthreads();

    float lsum = 0.0f;                 // accumulates w * log2(p)
    unsigned int lcnt = 0u;

    const int i = (blockIdx.x * THREADS + threadIdx.x) * EPT;

    if (i + EPT <= n) {
        // Phase A: 6 independent coalesced 128-bit loads
        int4   t4a = *reinterpret_cast<const int4*>(target + i);
        int4   t4b = *reinterpret_cast<const int4*>(target + i + 4);
        int4   c4a = *reinterpret_cast<const int4*>(cluster + i);
        int4   c4b = *reinterpret_cast<const int4*>(cluster + i + 4);
        float4 w4a = *reinterpret_cast<const float4*>(weight + i);
        float4 w4b = *reinterpret_cast<const float4*>(weight + i + 4);

        int   t[EPT] = {t4a.x, t4a.y, t4a.z, t4a.w, t4b.x, t4b.y, t4b.z, t4b.w};
        int   c[EPT] = {c4a.x, c4a.y, c4a.z, c4a.w, c4b.x, c4b.y, c4b.z, c4b.w};
        float w[EPT] = {w4a.x, w4a.y, w4a.z, w4a.w, w4b.x, w4b.y, w4b.z, w4b.w};

        // Phase B1: background LDG, branchless; inactive lanes -> input[0]
        // (single broadcast sector per warp-instr), 8 loads in flight
        float pbg[EPT];
        #pragma unroll
        for (int k = 0; k < EPT; k++) {
            const float* a = (t[k] == 0)
                           ? input + (long long)(i + k) * C_CLASSES
                           : input;
            pbg[k] = __ldg(a);
        }
        // Phase B2: foreground gather from smem (bank-conflict cost only)
        float pfg[EPT];
        #pragma unroll
        for (int k = 0; k < EPT; k++) {
            pfg[k] = pc_s[c[k] & (NUM_CLUSTERS - 1)];
        }

        // Phase C: select + log2 + masked accumulate
        #pragma unroll
        for (int k = 0; k < EPT; k++) {
            float p = (t[k] == 0) ? pbg[k] : pfg[k];
            bool valid = (t[k] != -1);
            float l = __log2f(fmaxf(p, EPS));
            lsum += valid ? w[k] * l : 0.0f;
            lcnt += valid ? 1u : 0u;
        }
    } else {
        for (int k = i; k < n; k++) {
            int tk = target[k];
            if (tk != -1) {
                float pk = (tk == 0) ? __ldg(input + (long long)k * C_CLASSES)
                                     : pc_s[cluster[k] & (NUM_CLUSTERS - 1)];
                lsum += weight[k] * __log2f(fmaxf(pk, EPS));
                lcnt++;
            }
        }
    }

    // warp reduction
    #pragma unroll
    for (int off = 16; off > 0; off >>= 1) {
        lsum += __shfl_xor_sync(0xFFFFFFFFu, lsum, off);
        lcnt += __shfl_xor_sync(0xFFFFFFFFu, lcnt, off);
    }

    // block reduction (8 warps)
    __shared__ float        s_sum[8];
    __shared__ unsigned int s_cnt[8];
    __shared__ int          s_is_last;
    int wid = threadIdx.x >> 5;
    int lid = threadIdx.x & 31;
    if (lid == 0) { s_sum[wid] = lsum; s_cnt[wid] = lcnt; }
    __syncthreads();
    if (threadIdx.x == 0) {
        float        bs = 0.0f;
        unsigned int bc = 0u;
        #pragma unroll
        for (int w8 = 0; w8 < 8; w8++) { bs += s_sum[w8]; bc += s_cnt[w8]; }
        // merge partials at the L2 coherence point (atomics bypass L1)
        atomicAdd(&g_sum, bs);
        atomicAdd(&g_cnt, bc);
        // release-only inc publishes the adds; wraps to 0 at gridDim.x-1
        // (self-reset, graph-replay deterministic); no acquire => no L1 flush
        unsigned int prev;
        asm volatile("atom.release.gpu.global.inc.u32 %0, [%1], %2;"
                     : "=r"(prev)
                     : "l"(&g_done), "r"(gridDim.x - 1)
                     : "memory");
        s_is_last = (prev == gridDim.x - 1) ? 1 : 0;
    }
    __syncthreads();

    if (s_is_last && threadIdx.x == 0) {
        // coherent reads at L2 — no acquire/L1-invalidate needed
        float        ts = atomicAdd(&g_sum, 0.0f);
        unsigned int tc = atomicAdd(&g_cnt, 0u);
        float nv = fmaxf((float)tc, 1.0f);
        *out = -(ts * LN2F) / nv;      // log2 -> ln conversion, once
        g_sum = 0.0f;                  // reset for next replay (kernel
        g_cnt = 0u;                    //  boundary orders visibility)
    }
}

extern "C" void kernel_launch(void* const* d_in, const int* in_sizes, int n_in,
                              void* d_out, int out_size) {
    const float* input   = (const float*)d_in[0];   // [N, 21]
    const float* weight  = (const float*)d_in[1];   // [N]
    const float* pc      = (const float*)d_in[2];   // [4096]
    const int*   target  = (const int*)d_in[3];     // [N] int32
    const int*   cluster = (const int*)d_in[4];     // [N] int32
    float* out = (float*)d_out;

    int n = in_sizes[1];   // weight element count == N

    int per_block = THREADS * EPT;                 // 2048
    int blocks = (n + per_block - 1) / per_block;  // 1024 for N=2M
    if (blocks < 1) blocks = 1;
    pcl_fused<<<blocks, THREADS>>>(input, weight, pc, target, cluster, n, out);
}